// round 13
// baseline (speedup 1.0000x reference)
#include <cuda_runtime.h>
#include <math.h>

#define TT 6
#define NN 50000
#define EE 800000
#define FF 32
#define HH 64
#define OUTC 16

#define TOTN (TT * NN)                 // 300000
#define SCAN_BLOCKS 1172               // ceil(TOTN/256)
#define AUX_PER_THREAD 5               // 256*5 = 1280 >= 1172
#define DEG_BPS   3125                 // EE/256
#define PLACE_BPS 3125
#define KK 96                          // FF + HH

// fused kernel config: 128 threads = 4 warps, 64 nodes per block
#define NPB 64
#define FUSED_BLOCKS 782               // ceil(NN/64)
#define AG_W 36                        // AGsh stride: 36%32=4 -> conflict-free a-frags
#define HS_W 68                        // Hsh/HRtf stride: 68%32=4 -> conflict-free
#define BSH_W 72                       // Bsh stride: 72%32=8 -> conflict-free b-frags
// smem words
#define SW_AG 0
#define SW_H  (SW_AG + NPB * AG_W)     // 2304
#define SW_HR (SW_H + NPB * HS_W)      // 6656
#define SW_B  (SW_HR + NPB * HS_W)     // 11008
#define SMEM_FUSED ((SW_B + KK * BSH_W) * 4)   // 71680 bytes

typedef unsigned long long u64;

// ---------------- scratch (device globals; no allocation allowed) ----------
__device__ __align__(16) float g_h   [(size_t)NN * HH];
__device__ int   g_deg [TOTN];
__device__ int   g_roff[TOTN];
__device__ int   g_cur [TOTN];
__device__ int   g_bsum[SCAN_BLOCKS];
__device__ u64   g_csrp[(size_t)TT * EE];   // packed (src, norm) per edge
__device__ float g_dinv[TOTN];

// folded weights, k-major, tf32 bits: k<FF -> (W@L_top) fold; k>=FF -> L_bot
__device__ __align__(16) unsigned g_Wmma[3][KK][HH];
__device__ float g_bv[3][HH];

__device__ __forceinline__ float sigmoidf_(float x) {
    return 1.0f / (1.0f + __expf(-x));
}

__device__ __forceinline__ unsigned f2tf(float f) {
    unsigned r; asm("cvt.rna.tf32.f32 %0, %1;" : "=r"(r) : "f"(f)); return r;
}

__device__ __forceinline__ void mma8(float* d,
                                     unsigned a0, unsigned a1, unsigned a2, unsigned a3,
                                     unsigned b0, unsigned b1) {
    asm volatile("mma.sync.aligned.m16n8k8.row.col.f32.tf32.tf32.f32 "
        "{%0,%1,%2,%3}, {%4,%5,%6,%7}, {%8,%9}, {%0,%1,%2,%3};"
        : "+f"(d[0]), "+f"(d[1]), "+f"(d[2]), "+f"(d[3])
        : "r"(a0), "r"(a1), "r"(a2), "r"(a3), "r"(b0), "r"(b1));
}

// ---------------- prep / clears ---------------------------------------------

__global__ void k_clear_int2() {
    unsigned i = blockIdx.x * blockDim.x + threadIdx.x;
    if (i < (unsigned)TOTN) { g_deg[i] = 0; g_cur[i] = 0; }
}

// one block per gate: build k-major tf32 weight panel + folded biases
__global__ void k_prep(const float* __restrict__ Wz, const float* __restrict__ bz,
                       const float* __restrict__ Wr, const float* __restrict__ br,
                       const float* __restrict__ Wh, const float* __restrict__ bh,
                       const float* __restrict__ Lz, const float* __restrict__ Lzb,
                       const float* __restrict__ Lr, const float* __restrict__ Lrb,
                       const float* __restrict__ Lh, const float* __restrict__ Lhb) {
    int g = blockIdx.x;
    int t = threadIdx.x;
    const float* W  = (g == 0) ? Wz  : (g == 1) ? Wr  : Wh;
    const float* b  = (g == 0) ? bz  : (g == 1) ? br  : bh;
    const float* L  = (g == 0) ? Lz  : (g == 1) ? Lr  : Lh;
    const float* Lb = (g == 0) ? Lzb : (g == 1) ? Lrb : Lhb;

    for (int e = t; e < KK * HH; e += 256) {
        int k = e >> 6, n = e & 63;
        float w;
        if (k < FF) {
            float s = 0.f;
            #pragma unroll 8
            for (int m = 0; m < HH; m++) s += __ldg(W + k * HH + m) * __ldg(L + m * HH + n);
            w = s;
        } else {
            w = __ldg(L + (k + 32) * HH + n);   // L_bot row (k-FF)+HH = k+32
        }
        g_Wmma[g][k][n] = f2tf(w);
    }
    if (t < HH) {
        float sb = __ldg(Lb + t);
        #pragma unroll 8
        for (int m = 0; m < HH; m++) sb += __ldg(b + m) * __ldg(L + m * HH + t);
        g_bv[g][t] = sb;
    }
}

// ---------------- degree ------------------------------------------------------

__global__ void k_deg_all(const int* __restrict__ ei) {
    int t = blockIdx.x / DEG_BPS;
    unsigned e = (blockIdx.x % DEG_BPS) * 256 + threadIdx.x;
    int d = __ldg(ei + (size_t)t * 2 * EE + EE + e);
    atomicAdd(&g_deg[t * NN + d], 1);
}

// ---------------- exclusive scan (+ dinv fused) -------------------------------

__global__ void k_scan_block() {
    __shared__ int sh[256];
    int tid = threadIdx.x;
    int i = blockIdx.x * 256 + tid;
    int v = (i < TOTN) ? g_deg[i] : 0;
    if (i < TOTN) g_dinv[i] = rsqrtf((float)(v + 1));
    sh[tid] = v;
    __syncthreads();
    #pragma unroll
    for (int off = 1; off < 256; off <<= 1) {
        int tv = (tid >= off) ? sh[tid - off] : 0;
        __syncthreads();
        sh[tid] += tv;
        __syncthreads();
    }
    if (i < TOTN) g_roff[i] = sh[tid] - v;
    if (tid == 255) g_bsum[blockIdx.x] = sh[255];
}

__global__ void k_scan_aux() {
    __shared__ int part[256];
    int tid = threadIdx.x;
    int start = tid * AUX_PER_THREAD;
    int loc[AUX_PER_THREAD];
    int vv [AUX_PER_THREAD];
    int sum = 0;
    #pragma unroll
    for (int j = 0; j < AUX_PER_THREAD; j++) {
        int idx = start + j;
        int v = (idx < SCAN_BLOCKS) ? g_bsum[idx] : 0;
        vv[j] = v;
        sum += v;
        loc[j] = sum;
    }
    part[tid] = sum;
    __syncthreads();
    #pragma unroll
    for (int off = 1; off < 256; off <<= 1) {
        int tv = (tid >= off) ? part[tid - off] : 0;
        __syncthreads();
        part[tid] += tv;
        __syncthreads();
    }
    int prev = (tid > 0) ? part[tid - 1] : 0;
    #pragma unroll
    for (int j = 0; j < AUX_PER_THREAD; j++) {
        int idx = start + j;
        if (idx < SCAN_BLOCKS) g_bsum[idx] = prev + loc[j] - vv[j];
    }
}

__global__ void k_scan_add() {
    int i = blockIdx.x * 256 + threadIdx.x;
    if (i < TOTN) g_roff[i] += g_bsum[blockIdx.x];
}

// ---------------- CSR placement (packed src + norm) -------------------------

__global__ void k_place(const int* __restrict__ ei) {
    int t = blockIdx.x / PLACE_BPS;
    unsigned e = (blockIdx.x % PLACE_BPS) * 256 + threadIdx.x;
    const int* base = ei + (size_t)t * 2 * EE;
    int s = __ldg(base + e);
    int d = __ldg(base + EE + e);
    int i = t * NN + d;
    int pos = g_roff[i] + atomicAdd(&g_cur[i], 1);
    float w = __ldg(&g_dinv[t * NN + s]) * __ldg(&g_dinv[i]);
    g_csrp[pos] = (u64)(unsigned)s | ((u64)__float_as_uint(w) << 32);
}

// ---------------- FUSED: in-block gather + 6-step GRU on tensor cores -------
// Block: 128 thr = 4 warps, 64 nodes. h lives in Hsh for all 6 steps.
// Per step: cooperative CSR gather -> AGsh (tf32), then 3 gate GEMMs (R11
// inner structure: m16n8k8 tf32 mma, warp = 16 nodes).

__global__ void __launch_bounds__(128) k_fused(const float* __restrict__ xs,
                                               const int* __restrict__ unused) {
    extern __shared__ float smem_f[];
    unsigned* AG   = (unsigned*)smem_f + SW_AG;   // [64][AG_W] tf32 aggx
    float*    Hsh  = smem_f + SW_H;               // [64][HS_W] fp32 h
    unsigned* HRtf = (unsigned*)smem_f + SW_HR;   // [64][HS_W] tf32 h*R
    unsigned* Bsh  = (unsigned*)smem_f + SW_B;    // [KK][BSH_W] tf32 weights

    int tid = threadIdx.x;
    int lane = tid & 31;
    int g4 = lane >> 2, t4 = lane & 3;
    int warp = tid >> 5;
    int wnb = warp * 16;

    int block_base = blockIdx.x * NPB;
    int r0 = block_base + wnb + g4;
    int r1 = r0 + 8;
    bool v0 = r0 < NN, v1 = r1 < NN;
    int l0 = wnb + g4, l1 = l0 + 8;

    // h = 0
    for (int i = tid; i < NPB * HS_W; i += 128) Hsh[i] = 0.f;

    float Z[8][4];
    float acc[8][4];

    for (int t = 0; t < TT; t++) {
        const float* x = xs + (size_t)t * NN * FF;
        __syncthreads();                  // prior step's AGsh reads complete

        // ---- in-block gather: AGsh[n][0..31] = (A_hat x)[node] (tf32) ----
        for (int task = tid; task < NPB * 8; task += 128) {
            int n = task >> 3, c = task & 7;
            int node = block_base + n;
            float4 a = make_float4(0.f, 0.f, 0.f, 0.f);
            if (node < NN) {
                int nf = t * NN + node;
                float dd = __ldg(&g_dinv[nf]);
                a = __ldg(reinterpret_cast<const float4*>(x + (size_t)node * FF) + c);
                float d2 = dd * dd;
                a.x *= d2; a.y *= d2; a.z *= d2; a.w *= d2;
                int beg = __ldg(&g_roff[nf]);
                int end = beg + __ldg(&g_deg[nf]);
                for (int p = beg; p < end; p++) {
                    u64 rec = __ldg(g_csrp + p);
                    int s = (int)(unsigned)(rec & 0xffffffffULL);
                    float ns = __uint_as_float((unsigned)(rec >> 32));
                    float4 v = __ldg(reinterpret_cast<const float4*>(x + (size_t)s * FF) + c);
                    a.x = fmaf(v.x, ns, a.x);
                    a.y = fmaf(v.y, ns, a.y);
                    a.z = fmaf(v.z, ns, a.z);
                    a.w = fmaf(v.w, ns, a.w);
                }
            }
            uint4 tf = make_uint4(f2tf(a.x), f2tf(a.y), f2tf(a.z), f2tf(a.w));
            *reinterpret_cast<uint4*>(&AG[n * AG_W + c * 4]) = tf;
        }

        for (int gate = 0; gate < 3; gate++) {
            __syncthreads();              // gather done / prior gate's Bsh reads done
            const unsigned* Wg = &g_Wmma[gate][0][0];
            for (int i = tid; i < KK * HH / 2; i += 128) {
                int k = i >> 5, j = (i & 31) * 2;
                uint2 w = *reinterpret_cast<const uint2*>(Wg + k * HH + j);
                Bsh[k * BSH_W + j]     = w.x;
                Bsh[k * BSH_W + j + 1] = w.y;
            }
            __syncthreads();

            #pragma unroll
            for (int nt = 0; nt < 8; nt++)
                #pragma unroll
                for (int q = 0; q < 4; q++) acc[nt][q] = 0.f;

            #pragma unroll
            for (int kk = 0; kk < 12; kk++) {
                unsigned a0, a1, a2, a3;
                if (kk < 4) {
                    int c0 = kk * 8 + t4, c1 = c0 + 4;
                    a0 = AG[l0 * AG_W + c0];
                    a1 = AG[l1 * AG_W + c0];
                    a2 = AG[l0 * AG_W + c1];
                    a3 = AG[l1 * AG_W + c1];
                } else {
                    int c0 = (kk - 4) * 8 + t4, c1 = c0 + 4;
                    if (gate < 2) {
                        a0 = f2tf(Hsh[l0 * HS_W + c0]);
                        a1 = f2tf(Hsh[l1 * HS_W + c0]);
                        a2 = f2tf(Hsh[l0 * HS_W + c1]);
                        a3 = f2tf(Hsh[l1 * HS_W + c1]);
                    } else {
                        a0 = HRtf[l0 * HS_W + c0];
                        a1 = HRtf[l1 * HS_W + c0];
                        a2 = HRtf[l0 * HS_W + c1];
                        a3 = HRtf[l1 * HS_W + c1];
                    }
                }
                #pragma unroll
                for (int nt = 0; nt < 8; nt++) {
                    unsigned b0 = Bsh[(kk * 8 + t4) * BSH_W + nt * 8 + g4];
                    unsigned b1 = Bsh[(kk * 8 + t4 + 4) * BSH_W + nt * 8 + g4];
                    mma8(acc[nt], a0, a1, a2, a3, b0, b1);
                }
            }

            if (gate == 0) {
                #pragma unroll
                for (int nt = 0; nt < 8; nt++) {
                    int col = nt * 8 + 2 * t4;
                    float ba = __ldg(&g_bv[0][col]), bb = __ldg(&g_bv[0][col + 1]);
                    Z[nt][0] = sigmoidf_(acc[nt][0] + ba);
                    Z[nt][1] = sigmoidf_(acc[nt][1] + bb);
                    Z[nt][2] = sigmoidf_(acc[nt][2] + ba);
                    Z[nt][3] = sigmoidf_(acc[nt][3] + bb);
                }
            } else if (gate == 1) {
                #pragma unroll
                for (int nt = 0; nt < 8; nt++) {
                    int col = nt * 8 + 2 * t4;
                    float ba = __ldg(&g_bv[1][col]), bb = __ldg(&g_bv[1][col + 1]);
                    float h00 = Hsh[l0 * HS_W + col];
                    float h01 = Hsh[l0 * HS_W + col + 1];
                    float h10 = Hsh[l1 * HS_W + col];
                    float h11 = Hsh[l1 * HS_W + col + 1];
                    HRtf[l0 * HS_W + col]     = f2tf(h00 * sigmoidf_(acc[nt][0] + ba));
                    HRtf[l0 * HS_W + col + 1] = f2tf(h01 * sigmoidf_(acc[nt][1] + bb));
                    HRtf[l1 * HS_W + col]     = f2tf(h10 * sigmoidf_(acc[nt][2] + ba));
                    HRtf[l1 * HS_W + col + 1] = f2tf(h11 * sigmoidf_(acc[nt][3] + bb));
                }
                __syncwarp();             // HRtf rows are warp-private
            } else {
                #pragma unroll
                for (int nt = 0; nt < 8; nt++) {
                    int col = nt * 8 + 2 * t4;
                    float ba = __ldg(&g_bv[2][col]), bb = __ldg(&g_bv[2][col + 1]);
                    float Ht0 = tanhf(acc[nt][0] + ba);
                    float Ht1 = tanhf(acc[nt][1] + bb);
                    float Ht2 = tanhf(acc[nt][2] + ba);
                    float Ht3 = tanhf(acc[nt][3] + bb);
                    float h00 = Hsh[l0 * HS_W + col];
                    float h01 = Hsh[l0 * HS_W + col + 1];
                    float h10 = Hsh[l1 * HS_W + col];
                    float h11 = Hsh[l1 * HS_W + col + 1];
                    Hsh[l0 * HS_W + col]     = Z[nt][0] * h00 + (1.f - Z[nt][0]) * Ht0;
                    Hsh[l0 * HS_W + col + 1] = Z[nt][1] * h01 + (1.f - Z[nt][1]) * Ht1;
                    Hsh[l1 * HS_W + col]     = Z[nt][2] * h10 + (1.f - Z[nt][2]) * Ht2;
                    Hsh[l1 * HS_W + col + 1] = Z[nt][3] * h11 + (1.f - Z[nt][3]) * Ht3;
                }
                __syncwarp();             // Hsh rows warp-private for next step
            }
        }
    }

    // write final h to global (coalesced float4)
    __syncthreads();
    for (int idx = tid; idx < NPB * (HH / 4); idx += 128) {
        int n = idx >> 4, k4 = idx & 15;
        int node = block_base + n;
        if (node < NN) {
            float4 v = *reinterpret_cast<const float4*>(&Hsh[n * HS_W + k4 * 4]);
            reinterpret_cast<float4*>(g_h + (size_t)node * HH)[k4] = v;
        }
    }
}

__global__ void k_out(const float* __restrict__ oW, const float* __restrict__ ob,
                      float* __restrict__ out) {
    unsigned idx = blockIdx.x * blockDim.x + threadIdx.x;
    if (idx >= (unsigned)(NN * OUTC)) return;
    int i = idx >> 4, j = idx & 15;
    const float* hr = g_h + (size_t)i * HH;
    float acc = __ldg(ob + j);
    #pragma unroll
    for (int k = 0; k < HH; k++) acc += hr[k] * __ldg(oW + k * OUTC + j);
    out[idx] = acc;
}

// ---------------- launch ----------------------------------------------------
extern "C" void kernel_launch(void* const* d_in, const int* in_sizes, int n_in,
                              void* d_out, int out_size) {
    const float* xs  = (const float*)d_in[0];
    const int*   ei  = (const int*)  d_in[1];
    const float* Wz  = (const float*)d_in[2];
    const float* bz  = (const float*)d_in[3];
    const float* Wr  = (const float*)d_in[4];
    const float* br  = (const float*)d_in[5];
    const float* Wh  = (const float*)d_in[6];
    const float* bh  = (const float*)d_in[7];
    const float* Lz  = (const float*)d_in[8];
    const float* Lzb = (const float*)d_in[9];
    const float* Lr  = (const float*)d_in[10];
    const float* Lrb = (const float*)d_in[11];
    const float* Lh  = (const float*)d_in[12];
    const float* Lhb = (const float*)d_in[13];
    const float* oW  = (const float*)d_in[14];
    const float* ob  = (const float*)d_in[15];
    float* out = (float*)d_out;

    cudaFuncSetAttribute(k_fused, cudaFuncAttributeMaxDynamicSharedMemorySize,
                         SMEM_FUSED);

    k_prep<<<3, 256>>>(Wz, bz, Wr, br, Wh, bh, Lz, Lzb, Lr, Lrb, Lh, Lhb);
    k_clear_int2<<<SCAN_BLOCKS, 256>>>();

    k_deg_all<<<TT * DEG_BPS, 256>>>(ei);
    k_scan_block<<<SCAN_BLOCKS, 256>>>();
    k_scan_aux<<<1, 256>>>();
    k_scan_add<<<SCAN_BLOCKS, 256>>>();
    k_place<<<TT * PLACE_BPS, 256>>>(ei);

    k_fused<<<FUSED_BLOCKS, 128, SMEM_FUSED>>>(xs, ei);

    k_out<<<(NN * OUTC + 255) / 256, 256>>>(oW, ob, out);
}

// round 14
// speedup vs baseline: 1.1772x; 1.1772x over previous
#include <cuda_runtime.h>
#include <math.h>

#define TT 6
#define NN 50000
#define EE 800000
#define FF 32
#define HH 64
#define OUTC 16

#define TOTN (TT * NN)                 // 300000
#define SCAN_BLOCKS 1172               // ceil(TOTN/256)
#define AUX_PER_THREAD 5               // 256*5 = 1280 >= 1172
#define DEG_BPS   3125                 // EE/256
#define PLACE_BPS 3125
#define GATH_T_BLOCKS 1563             // ceil(NN*8/256), one timestep
#define KK 96                          // FF + HH

// gate-GEMM (mma) config — R11 champion layout
#define NPB 128                        // nodes per block (8 warps x 16)
#define GATE_BLOCKS 391                // ceil(NN/128)
#define BSH_W 72                       // Bsh stride (words): 72%32=8 -> conflict-free b-frags
#define HR_W  68                       // HRw stride (words): 68%32=4 -> conflict-free a-frags
#define SMEM_GATES ((KK * BSH_W + 8 * 16 * HR_W) * 4)   // 62464 bytes

typedef unsigned long long u64;

// ---------------- scratch (device globals; no allocation allowed) ----------
__device__ __align__(16) float g_aggx[(size_t)TT * NN * FF];  // A_hat@X, all steps
__device__ __align__(16) float g_h   [(size_t)NN * HH];
__device__ int   g_deg [TOTN];
__device__ int   g_roff[TOTN];
__device__ int   g_cur [TOTN];
__device__ int   g_bsum[SCAN_BLOCKS];
__device__ u64   g_csrp[(size_t)TT * EE];   // packed (src, norm) per edge
__device__ float g_dinv[TOTN];

// folded weights, k-major, tf32 bits: k<FF -> (W@L_top) fold; k>=FF -> L_bot
__device__ __align__(16) unsigned g_Wmma[3][KK][HH];
__device__ float g_bv[3][HH];

__device__ __forceinline__ float sigmoidf_(float x) {
    return 1.0f / (1.0f + __expf(-x));
}

__device__ __forceinline__ unsigned f2tf(float f) {
    unsigned r; asm("cvt.rna.tf32.f32 %0, %1;" : "=r"(r) : "f"(f)); return r;
}

__device__ __forceinline__ void mma8(float* d,
                                     unsigned a0, unsigned a1, unsigned a2, unsigned a3,
                                     unsigned b0, unsigned b1) {
    asm volatile("mma.sync.aligned.m16n8k8.row.col.f32.tf32.tf32.f32 "
        "{%0,%1,%2,%3}, {%4,%5,%6,%7}, {%8,%9}, {%0,%1,%2,%3};"
        : "+f"(d[0]), "+f"(d[1]), "+f"(d[2]), "+f"(d[3])
        : "r"(a0), "r"(a1), "r"(a2), "r"(a3), "r"(b0), "r"(b1));
}

// ---------------- prep / clears ---------------------------------------------

__global__ void k_clear_h() {
    unsigned idx = blockIdx.x * blockDim.x + threadIdx.x;
    if (idx < (unsigned)(NN * HH)) g_h[idx] = 0.0f;
}

__global__ void k_clear_int2() {
    unsigned i = blockIdx.x * blockDim.x + threadIdx.x;
    if (i < (unsigned)TOTN) { g_deg[i] = 0; g_cur[i] = 0; }
}

// one block per gate: build k-major tf32 weight panel + folded biases
__global__ void k_prep(const float* __restrict__ Wz, const float* __restrict__ bz,
                       const float* __restrict__ Wr, const float* __restrict__ br,
                       const float* __restrict__ Wh, const float* __restrict__ bh,
                       const float* __restrict__ Lz, const float* __restrict__ Lzb,
                       const float* __restrict__ Lr, const float* __restrict__ Lrb,
                       const float* __restrict__ Lh, const float* __restrict__ Lhb) {
    int g = blockIdx.x;
    int t = threadIdx.x;
    const float* W  = (g == 0) ? Wz  : (g == 1) ? Wr  : Wh;
    const float* b  = (g == 0) ? bz  : (g == 1) ? br  : bh;
    const float* L  = (g == 0) ? Lz  : (g == 1) ? Lr  : Lh;
    const float* Lb = (g == 0) ? Lzb : (g == 1) ? Lrb : Lhb;

    for (int e = t; e < KK * HH; e += 256) {
        int k = e >> 6, n = e & 63;
        float w;
        if (k < FF) {
            float s = 0.f;
            #pragma unroll 8
            for (int m = 0; m < HH; m++) s += __ldg(W + k * HH + m) * __ldg(L + m * HH + n);
            w = s;
        } else {
            w = __ldg(L + (k + 32) * HH + n);   // L_bot row (k-FF)+HH = k+32
        }
        g_Wmma[g][k][n] = f2tf(w);
    }
    if (t < HH) {
        float sb = __ldg(Lb + t);
        #pragma unroll 8
        for (int m = 0; m < HH; m++) sb += __ldg(b + m) * __ldg(L + m * HH + t);
        g_bv[g][t] = sb;
    }
}

// ---------------- degree ------------------------------------------------------

__global__ void k_deg_all(const int* __restrict__ ei) {
    int t = blockIdx.x / DEG_BPS;
    unsigned e = (blockIdx.x % DEG_BPS) * 256 + threadIdx.x;
    int d = __ldg(ei + (size_t)t * 2 * EE + EE + e);
    atomicAdd(&g_deg[t * NN + d], 1);
}

// ---------------- exclusive scan (+ dinv fused) -------------------------------

__global__ void k_scan_block() {
    __shared__ int sh[256];
    int tid = threadIdx.x;
    int i = blockIdx.x * 256 + tid;
    int v = (i < TOTN) ? g_deg[i] : 0;
    if (i < TOTN) g_dinv[i] = rsqrtf((float)(v + 1));
    sh[tid] = v;
    __syncthreads();
    #pragma unroll
    for (int off = 1; off < 256; off <<= 1) {
        int tv = (tid >= off) ? sh[tid - off] : 0;
        __syncthreads();
        sh[tid] += tv;
        __syncthreads();
    }
    if (i < TOTN) g_roff[i] = sh[tid] - v;
    if (tid == 255) g_bsum[blockIdx.x] = sh[255];
}

__global__ void k_scan_aux() {
    __shared__ int part[256];
    int tid = threadIdx.x;
    int start = tid * AUX_PER_THREAD;
    int loc[AUX_PER_THREAD];
    int vv [AUX_PER_THREAD];
    int sum = 0;
    #pragma unroll
    for (int j = 0; j < AUX_PER_THREAD; j++) {
        int idx = start + j;
        int v = (idx < SCAN_BLOCKS) ? g_bsum[idx] : 0;
        vv[j] = v;
        sum += v;
        loc[j] = sum;
    }
    part[tid] = sum;
    __syncthreads();
    #pragma unroll
    for (int off = 1; off < 256; off <<= 1) {
        int tv = (tid >= off) ? part[tid - off] : 0;
        __syncthreads();
        part[tid] += tv;
        __syncthreads();
    }
    int prev = (tid > 0) ? part[tid - 1] : 0;
    #pragma unroll
    for (int j = 0; j < AUX_PER_THREAD; j++) {
        int idx = start + j;
        if (idx < SCAN_BLOCKS) g_bsum[idx] = prev + loc[j] - vv[j];
    }
}

__global__ void k_scan_add() {
    int i = blockIdx.x * 256 + threadIdx.x;
    if (i < TOTN) g_roff[i] += g_bsum[blockIdx.x];
}

// ---------------- CSR placement (packed src + norm) -------------------------

__global__ void k_place(const int* __restrict__ ei) {
    int t = blockIdx.x / PLACE_BPS;
    unsigned e = (blockIdx.x % PLACE_BPS) * 256 + threadIdx.x;
    const int* base = ei + (size_t)t * 2 * EE;
    int s = __ldg(base + e);
    int d = __ldg(base + EE + e);
    int i = t * NN + d;
    int pos = g_roff[i] + atomicAdd(&g_cur[i], 1);
    float w = __ldg(&g_dinv[t * NN + s]) * __ldg(&g_dinv[i]);
    g_csrp[pos] = (u64)(unsigned)s | ((u64)__float_as_uint(w) << 32);
}

// ---------------- pull-mode gather, one timestep ------------------------------

__global__ void k_gather_t(const float* __restrict__ xs, int t) {
    unsigned idx = blockIdx.x * 256 + threadIdx.x;   // < NN*8
    if (idx >= (unsigned)NN * 8u) return;
    unsigned node = idx >> 3;
    unsigned c    = idx & 7u;
    unsigned nf   = t * NN + node;
    const float* x = xs + (size_t)t * NN * FF;

    float dd = g_dinv[nf];
    float4 acc = __ldg(reinterpret_cast<const float4*>(x + (size_t)node * FF) + c);
    float d2 = dd * dd;
    acc.x *= d2; acc.y *= d2; acc.z *= d2; acc.w *= d2;

    int beg = g_roff[nf];
    int end = beg + g_deg[nf];
    for (int p = beg; p < end; p++) {
        u64 rec = __ldg(g_csrp + p);
        int s = (int)(unsigned)(rec & 0xffffffffULL);
        float ns = __uint_as_float((unsigned)(rec >> 32));
        float4 v = __ldg(reinterpret_cast<const float4*>(x + (size_t)s * FF) + c);
        acc.x = fmaf(v.x, ns, acc.x);
        acc.y = fmaf(v.y, ns, acc.y);
        acc.z = fmaf(v.z, ns, acc.z);
        acc.w = fmaf(v.w, ns, acc.w);
    }
    reinterpret_cast<float4*>(g_aggx + (size_t)nf * FF)[c] = acc;
}

// ---------------- GRU gates on tensor cores (R11 champion version) -----------

__global__ void __launch_bounds__(256) k_gates_mma(int t) {
    extern __shared__ unsigned smem_u[];
    unsigned* Bsh = smem_u;                                        // [KK][BSH_W]
    unsigned* HRw = smem_u + KK * BSH_W + (threadIdx.x >> 5) * (16 * HR_W);

    int tid = threadIdx.x;
    int lane = tid & 31;
    int g4 = lane >> 2, t4 = lane & 3;
    int warp = tid >> 5;

    const float* aggx_t = g_aggx + (size_t)t * NN * FF;

    int node0 = blockIdx.x * NPB + warp * 16;
    int r0 = node0 + g4;
    int r1 = r0 + 8;
    bool v0 = r0 < NN, v1 = r1 < NN;

    // resident aggx A-fragments (k-steps 0..3)
    unsigned Aa[4][4];
    #pragma unroll
    for (int kk = 0; kk < 4; kk++) {
        int c0 = kk * 8 + t4, c1 = c0 + 4;
        Aa[kk][0] = f2tf(v0 ? __ldg(aggx_t + (size_t)r0 * FF + c0) : 0.f);
        Aa[kk][1] = f2tf(v1 ? __ldg(aggx_t + (size_t)r1 * FF + c0) : 0.f);
        Aa[kk][2] = f2tf(v0 ? __ldg(aggx_t + (size_t)r0 * FF + c1) : 0.f);
        Aa[kk][3] = f2tf(v1 ? __ldg(aggx_t + (size_t)r1 * FF + c1) : 0.f);
    }

    float Z[8][4];
    float acc[8][4];

    for (int gate = 0; gate < 3; gate++) {
        __syncthreads();                       // protect Bsh (and HRw ordering)
        const unsigned* Wg = &g_Wmma[gate][0][0];
        for (int i = tid; i < KK * HH / 2; i += 256) {
            int k = i >> 5, j = (i & 31) * 2;
            uint2 w = *reinterpret_cast<const uint2*>(Wg + k * HH + j);
            Bsh[k * BSH_W + j]     = w.x;
            Bsh[k * BSH_W + j + 1] = w.y;
        }
        __syncthreads();

        #pragma unroll
        for (int nt = 0; nt < 8; nt++)
            #pragma unroll
            for (int q = 0; q < 4; q++) acc[nt][q] = 0.f;

        #pragma unroll
        for (int kk = 0; kk < 12; kk++) {
            unsigned a0, a1, a2, a3;
            if (kk < 4) {
                a0 = Aa[kk][0]; a1 = Aa[kk][1]; a2 = Aa[kk][2]; a3 = Aa[kk][3];
            } else if (gate < 2) {
                int c0 = (kk - 4) * 8 + t4, c1 = c0 + 4;
                a0 = f2tf(v0 ? __ldg(g_h + (size_t)r0 * HH + c0) : 0.f);
                a1 = f2tf(v1 ? __ldg(g_h + (size_t)r1 * HH + c0) : 0.f);
                a2 = f2tf(v0 ? __ldg(g_h + (size_t)r0 * HH + c1) : 0.f);
                a3 = f2tf(v1 ? __ldg(g_h + (size_t)r1 * HH + c1) : 0.f);
            } else {
                int c0 = (kk - 4) * 8 + t4, c1 = c0 + 4;
                a0 = HRw[g4 * HR_W + c0];
                a1 = HRw[(g4 + 8) * HR_W + c0];
                a2 = HRw[g4 * HR_W + c1];
                a3 = HRw[(g4 + 8) * HR_W + c1];
            }
            #pragma unroll
            for (int nt = 0; nt < 8; nt++) {
                unsigned b0 = Bsh[(kk * 8 + t4) * BSH_W + nt * 8 + g4];
                unsigned b1 = Bsh[(kk * 8 + t4 + 4) * BSH_W + nt * 8 + g4];
                mma8(acc[nt], a0, a1, a2, a3, b0, b1);
            }
        }

        if (gate == 0) {
            #pragma unroll
            for (int nt = 0; nt < 8; nt++) {
                int col = nt * 8 + 2 * t4;
                float ba = __ldg(&g_bv[0][col]), bb = __ldg(&g_bv[0][col + 1]);
                Z[nt][0] = sigmoidf_(acc[nt][0] + ba);
                Z[nt][1] = sigmoidf_(acc[nt][1] + bb);
                Z[nt][2] = sigmoidf_(acc[nt][2] + ba);
                Z[nt][3] = sigmoidf_(acc[nt][3] + bb);
            }
        } else if (gate == 1) {
            #pragma unroll
            for (int nt = 0; nt < 8; nt++) {
                int col = nt * 8 + 2 * t4;
                float ba = __ldg(&g_bv[1][col]), bb = __ldg(&g_bv[1][col + 1]);
                float h00 = v0 ? g_h[(size_t)r0 * HH + col]     : 0.f;
                float h01 = v0 ? g_h[(size_t)r0 * HH + col + 1] : 0.f;
                float h10 = v1 ? g_h[(size_t)r1 * HH + col]     : 0.f;
                float h11 = v1 ? g_h[(size_t)r1 * HH + col + 1] : 0.f;
                HRw[g4 * HR_W + col]           = f2tf(h00 * sigmoidf_(acc[nt][0] + ba));
                HRw[g4 * HR_W + col + 1]       = f2tf(h01 * sigmoidf_(acc[nt][1] + bb));
                HRw[(g4 + 8) * HR_W + col]     = f2tf(h10 * sigmoidf_(acc[nt][2] + ba));
                HRw[(g4 + 8) * HR_W + col + 1] = f2tf(h11 * sigmoidf_(acc[nt][3] + bb));
            }
        } else {
            #pragma unroll
            for (int nt = 0; nt < 8; nt++) {
                int col = nt * 8 + 2 * t4;
                float ba = __ldg(&g_bv[2][col]), bb = __ldg(&g_bv[2][col + 1]);
                float Ht0 = tanhf(acc[nt][0] + ba);
                float Ht1 = tanhf(acc[nt][1] + bb);
                float Ht2 = tanhf(acc[nt][2] + ba);
                float Ht3 = tanhf(acc[nt][3] + bb);
                if (v0) {
                    float h00 = g_h[(size_t)r0 * HH + col];
                    float h01 = g_h[(size_t)r0 * HH + col + 1];
                    float o0 = Z[nt][0] * h00 + (1.f - Z[nt][0]) * Ht0;
                    float o1 = Z[nt][1] * h01 + (1.f - Z[nt][1]) * Ht1;
                    *reinterpret_cast<float2*>(g_h + (size_t)r0 * HH + col) = make_float2(o0, o1);
                }
                if (v1) {
                    float h10 = g_h[(size_t)r1 * HH + col];
                    float h11 = g_h[(size_t)r1 * HH + col + 1];
                    float o2 = Z[nt][2] * h10 + (1.f - Z[nt][2]) * Ht2;
                    float o3 = Z[nt][3] * h11 + (1.f - Z[nt][3]) * Ht3;
                    *reinterpret_cast<float2*>(g_h + (size_t)r1 * HH + col) = make_float2(o2, o3);
                }
            }
        }
    }
}

__global__ void k_out(const float* __restrict__ oW, const float* __restrict__ ob,
                      float* __restrict__ out) {
    unsigned idx = blockIdx.x * blockDim.x + threadIdx.x;
    if (idx >= (unsigned)(NN * OUTC)) return;
    int i = idx >> 4, j = idx & 15;
    const float* hr = g_h + (size_t)i * HH;
    float acc = __ldg(ob + j);
    #pragma unroll
    for (int k = 0; k < HH; k++) acc += hr[k] * __ldg(oW + k * OUTC + j);
    out[idx] = acc;
}

// ---------------- launch (fork/join multi-stream graph) ----------------------
extern "C" void kernel_launch(void* const* d_in, const int* in_sizes, int n_in,
                              void* d_out, int out_size) {
    const float* xs  = (const float*)d_in[0];
    const int*   ei  = (const int*)  d_in[1];
    const float* Wz  = (const float*)d_in[2];
    const float* bz  = (const float*)d_in[3];
    const float* Wr  = (const float*)d_in[4];
    const float* br  = (const float*)d_in[5];
    const float* Wh  = (const float*)d_in[6];
    const float* bh  = (const float*)d_in[7];
    const float* Lz  = (const float*)d_in[8];
    const float* Lzb = (const float*)d_in[9];
    const float* Lr  = (const float*)d_in[10];
    const float* Lrb = (const float*)d_in[11];
    const float* Lh  = (const float*)d_in[12];
    const float* Lhb = (const float*)d_in[13];
    const float* oW  = (const float*)d_in[14];
    const float* ob  = (const float*)d_in[15];
    float* out = (float*)d_out;

    // one-time host resources (created on the uncaptured correctness call)
    static cudaStream_t sB = nullptr;
    static cudaEvent_t evStart = nullptr, evPre = nullptr, evPrep = nullptr;
    static cudaEvent_t evG[TT] = {};
    static bool inited = false;
    if (!inited) {
        cudaStreamCreateWithFlags(&sB, cudaStreamNonBlocking);
        cudaEventCreateWithFlags(&evStart, cudaEventDisableTiming);
        cudaEventCreateWithFlags(&evPre, cudaEventDisableTiming);
        cudaEventCreateWithFlags(&evPrep, cudaEventDisableTiming);
        for (int t = 0; t < TT; t++)
            cudaEventCreateWithFlags(&evG[t], cudaEventDisableTiming);
        cudaFuncSetAttribute(k_gates_mma, cudaFuncAttributeMaxDynamicSharedMemorySize,
                             SMEM_GATES);
        inited = true;
    }

    // fork stream B off the capture origin (default stream)
    cudaEventRecord(evStart, 0);
    cudaStreamWaitEvent(sB, evStart, 0);

    // stream B: weight prep (independent of edge pipeline)
    k_prep<<<3, 256, 0, sB>>>(Wz, bz, Wr, br, Wh, bh, Lz, Lzb, Lr, Lrb, Lh, Lhb);
    cudaEventRecord(evPrep, sB);

    // default stream: edge preprocessing chain
    k_clear_h<<<(NN * HH + 255) / 256, 256>>>();
    k_clear_int2<<<SCAN_BLOCKS, 256>>>();
    k_deg_all<<<TT * DEG_BPS, 256>>>(ei);
    k_scan_block<<<SCAN_BLOCKS, 256>>>();
    k_scan_aux<<<1, 256>>>();
    k_scan_add<<<SCAN_BLOCKS, 256>>>();
    k_place<<<TT * PLACE_BPS, 256>>>(ei);
    cudaEventRecord(evPre, 0);

    // stream B: per-timestep gathers (after place; prep already on sB)
    cudaStreamWaitEvent(sB, evPre, 0);
    for (int t = 0; t < TT; t++) {
        k_gather_t<<<GATH_T_BLOCKS, 256, 0, sB>>>(xs, t);
        cudaEventRecord(evG[t], sB);
    }

    // default stream: recurrent gate chain, each step gated on its gather
    cudaStreamWaitEvent(0, evPrep, 0);
    for (int t = 0; t < TT; t++) {
        cudaStreamWaitEvent(0, evG[t], 0);
        k_gates_mma<<<GATE_BLOCKS, 256, SMEM_GATES>>>(t);
    }

    k_out<<<(NN * OUTC + 255) / 256, 256>>>(oW, ob, out);
}